// round 8
// baseline (speedup 1.0000x reference)
#include <cuda_runtime.h>
#include <cstdint>

// Problem constants
#define N_TOT   8192
#define F_DIM   128
#define NCHUNK  8                   // n-rows per CTA
#define TILE_F4 (9 * F_DIM)         // 1152 float4 = 18432 B = one n's full output

// out[n,a,b,f,uv] = 0.75*(x[n,a,f,u]*y[n,b,f,v] + x[n,b,f,u]*y[n,a,f,v])
//                 - 0.5*z[n,f,uv]*(a==b)
// x: [N,3,F,2]  y: [N,3,F,2]  z: [N,F,4]  out: [N,3,3,F,4]
//
// TMA bulk-store variant: out[n,:,:,:,:] is 18 KB contiguous. Each CTA
// (128 threads, one per f) computes a whole n-row into SMEM and drains it
// with a single cp.async.bulk 18 KB burst, double-buffered across steps.
// Writes leave the SM as few huge contiguous transfers instead of per-warp
// 1 KB STG segments interleaved with reads.

__global__ __launch_bounds__(F_DIM) void tp_block2_kernel(
    const float2* __restrict__ x,   // viewed as [N,3,F] float2
    const float2* __restrict__ y,   // viewed as [N,3,F] float2
    const float4* __restrict__ z,   // viewed as [N,F] float4
    float4* __restrict__ out)       // viewed as [N,3,3,F] float4
{
    __shared__ float4 buf[2][TILE_F4];   // 36 KB, double-buffered

    const int f  = threadIdx.x;          // 0..127
    const int n0 = blockIdx.x * NCHUNK;

    const float c1 = 0.75f;              // NORM_112
    const float c2 = 0.5f;               // 0.75 * 2/3

    for (int s = 0; s < NCHUNK; s++) {
        const int n     = n0 + s;
        const int phase = s & 1;

        // Before overwriting buf[phase], the bulk store issued at step s-2
        // (which read this buffer) must have completed its SMEM reads.
        if (s >= 2 && threadIdx.x == 0)
            asm volatile("cp.async.bulk.wait_group 1;" ::: "memory");
        __syncthreads();

        // Coalesced loads: 6x LDG.64 + 1x LDG.128 per thread.
        int base = (n * 3) * F_DIM + f;
        float2 xa[3], yb[3];
        xa[0] = x[base];
        xa[1] = x[base + F_DIM];
        xa[2] = x[base + 2 * F_DIM];
        yb[0] = y[base];
        yb[1] = y[base + F_DIM];
        yb[2] = y[base + 2 * F_DIM];
        float4 zv = z[n * F_DIM + f];

        float4 zc;
        zc.x = c2 * zv.x; zc.y = c2 * zv.y; zc.z = c2 * zv.z; zc.w = c2 * zv.w;

#pragma unroll
        for (int a = 0; a < 3; a++) {
#pragma unroll
            for (int b = 0; b < 3; b++) {
                float4 v;
                v.x = c1 * (xa[a].x * yb[b].x + xa[b].x * yb[a].x);
                v.y = c1 * (xa[a].x * yb[b].y + xa[b].x * yb[a].y);
                v.z = c1 * (xa[a].y * yb[b].x + xa[b].y * yb[a].x);
                v.w = c1 * (xa[a].y * yb[b].y + xa[b].y * yb[a].y);
                if (a == b) {
                    v.x -= zc.x; v.y -= zc.y; v.z -= zc.z; v.w -= zc.w;
                }
                buf[phase][(a * 3 + b) * F_DIM + f] = v;   // STS.128, conflict-free
            }
        }
        __syncthreads();

        // One thread drains the whole 18 KB n-row as a single bulk store.
        if (threadIdx.x == 0) {
            asm volatile("fence.proxy.async.shared::cta;" ::: "memory");
            uint32_t saddr = (uint32_t)__cvta_generic_to_shared(&buf[phase][0]);
            const float4* gdst = out + (size_t)n * TILE_F4;
            int bytes = TILE_F4 * 16;
            asm volatile(
                "cp.async.bulk.global.shared::cta.bulk_group [%0], [%1], %2;"
                :: "l"(gdst), "r"(saddr), "r"(bytes) : "memory");
            asm volatile("cp.async.bulk.commit_group;" ::: "memory");
        }
    }

    // Drain all outstanding bulk stores before exit.
    if (threadIdx.x == 0)
        asm volatile("cp.async.bulk.wait_group 0;" ::: "memory");
    __syncthreads();
}

extern "C" void kernel_launch(void* const* d_in, const int* in_sizes, int n_in,
                              void* d_out, int out_size) {
    const float2* x = (const float2*)d_in[0];
    const float2* y = (const float2*)d_in[1];
    const float4* z = (const float4*)d_in[2];
    // d_in[3] is eye (identity) — value known, not needed.
    float4* out = (float4*)d_out;

    const int blocks = N_TOT / NCHUNK;   // 1024
    tp_block2_kernel<<<blocks, F_DIM>>>(x, y, z, out);
}

// round 9
// speedup vs baseline: 1.0902x; 1.0902x over previous
#include <cuda_runtime.h>

// Problem constants
#define N_TOT 8192
#define F_DIM 128
#define FP    (F_DIM / 2)            // 64 f-pairs
#define NU    (N_TOT / 2 * FP)       // 262,144 threads: each handles (n, n+1) x f-pair

// out[n,a,b,f,uv] = 0.75*(x[n,a,f,u]*y[n,b,f,v] + x[n,b,f,u]*y[n,a,f,v])
//                 - 0.5*z[n,f,uv]*(a==b)
// x: [N,3,F,2]  y: [N,3,F,2]  z: [N,F,4]  out: [N,3,3,F,4]
//
// Burst-batched variant: each thread handles TWO adjacent n (and an f-pair).
// All 14 loads (12x LDG.128 + 2x LDG.256) are front-batched, then all 18
// STG.256 stores issue back-to-back. Each warp scheduler thus presents long
// homogeneous read bursts followed by long write bursts, maximizing the run
// length between DRAM bus turnarounds.

__device__ __forceinline__ void stg256(float4* p, const float4& v0, const float4& v1) {
    asm volatile(
        "st.global.v8.f32 [%0], {%1, %2, %3, %4, %5, %6, %7, %8};"
        :: "l"(p),
           "f"(v0.x), "f"(v0.y), "f"(v0.z), "f"(v0.w),
           "f"(v1.x), "f"(v1.y), "f"(v1.z), "f"(v1.w)
        : "memory");
}

__device__ __forceinline__ void ldg256(const float4* p, float4& v0, float4& v1) {
    asm volatile(
        "ld.global.nc.v8.f32 {%0, %1, %2, %3, %4, %5, %6, %7}, [%8];"
        : "=f"(v0.x), "=f"(v0.y), "=f"(v0.z), "=f"(v0.w),
          "=f"(v1.x), "=f"(v1.y), "=f"(v1.z), "=f"(v1.w)
        : "l"(p));
}

// Compute one (a,b) tile's pair of output float4s for one n.
__device__ __forceinline__ void tile_pair(
    const float4& xaa, const float4& xab,    // xa[a], xa[b]
    const float4& yba, const float4& ybb,    // yb[a], yb[b]
    float4& v0, float4& v1)
{
    // f0: .x/.y halves
    v0.x = xaa.x * ybb.x + xab.x * yba.x;
    v0.y = xaa.x * ybb.y + xab.x * yba.y;
    v0.z = xaa.y * ybb.x + xab.y * yba.x;
    v0.w = xaa.y * ybb.y + xab.y * yba.y;
    // f1: .z/.w halves
    v1.x = xaa.z * ybb.z + xab.z * yba.z;
    v1.y = xaa.z * ybb.w + xab.z * yba.w;
    v1.z = xaa.w * ybb.z + xab.w * yba.z;
    v1.w = xaa.w * ybb.w + xab.w * yba.w;
}

__global__ __launch_bounds__(128) void tp_block2_kernel(
    const float4* __restrict__ x,   // viewed as [N,3,FP] float4
    const float4* __restrict__ y,   // viewed as [N,3,FP] float4
    const float4* __restrict__ z,   // viewed as [N,F] float4
    float4* __restrict__ out)       // viewed as [N,3,3,F] float4
{
    int idx = blockIdx.x * blockDim.x + threadIdx.x;
    if (idx >= NU) return;
    int half = idx / FP;            // 0..4095
    int fp   = idx - half * FP;     // f-pair index; f0 = 2*fp, f1 = 2*fp+1
    int n0   = 2 * half;            // handles n0 and n0+1

    const float c1 = 0.75f;         // NORM_112
    const float c2 = 0.5f;          // 0.75 * 2/3

    // ---- READ BURST: 12x LDG.128 + 2x LDG.256, all independent ----
    int base0 = (n0 * 3) * FP + fp;
    int base1 = base0 + 3 * FP;
    float4 xa0[3], yb0[3], xa1[3], yb1[3];
    xa0[0] = x[base0];            xa0[1] = x[base0 + FP];   xa0[2] = x[base0 + 2 * FP];
    xa1[0] = x[base1];            xa1[1] = x[base1 + FP];   xa1[2] = x[base1 + 2 * FP];
    yb0[0] = y[base0];            yb0[1] = y[base0 + FP];   yb0[2] = y[base0 + 2 * FP];
    yb1[0] = y[base1];            yb1[1] = y[base1 + FP];   yb1[2] = y[base1 + 2 * FP];
    float4 za0, za1, zb0, zb1;
    ldg256(&z[n0 * F_DIM + 2 * fp], za0, za1);
    ldg256(&z[(n0 + 1) * F_DIM + 2 * fp], zb0, zb1);

    // Fold the 0.75 into x once.
#pragma unroll
    for (int a = 0; a < 3; a++) {
        xa0[a].x *= c1; xa0[a].y *= c1; xa0[a].z *= c1; xa0[a].w *= c1;
        xa1[a].x *= c1; xa1[a].y *= c1; xa1[a].z *= c1; xa1[a].w *= c1;
    }
    // Pre-scale z (diagonal term).
    float4 zc[4];
    zc[0].x = c2 * za0.x; zc[0].y = c2 * za0.y; zc[0].z = c2 * za0.z; zc[0].w = c2 * za0.w;
    zc[1].x = c2 * za1.x; zc[1].y = c2 * za1.y; zc[1].z = c2 * za1.z; zc[1].w = c2 * za1.w;
    zc[2].x = c2 * zb0.x; zc[2].y = c2 * zb0.y; zc[2].z = c2 * zb0.z; zc[2].w = c2 * zb0.w;
    zc[3].x = c2 * zb1.x; zc[3].y = c2 * zb1.y; zc[3].z = c2 * zb1.z; zc[3].w = c2 * zb1.w;

    // ---- WRITE BURST: 18x STG.256 back-to-back ----
    int ob0 = (n0 * 9) * F_DIM + 2 * fp;
    int ob1 = ob0 + 9 * F_DIM;
#pragma unroll
    for (int a = 0; a < 3; a++) {
#pragma unroll
        for (int b = 0; b < 3; b++) {
            float4 v0, v1, w0, w1;
            tile_pair(xa0[a], xa0[b], yb0[a], yb0[b], v0, v1);
            tile_pair(xa1[a], xa1[b], yb1[a], yb1[b], w0, w1);
            if (a == b) {
                v0.x -= zc[0].x; v0.y -= zc[0].y; v0.z -= zc[0].z; v0.w -= zc[0].w;
                v1.x -= zc[1].x; v1.y -= zc[1].y; v1.z -= zc[1].z; v1.w -= zc[1].w;
                w0.x -= zc[2].x; w0.y -= zc[2].y; w0.z -= zc[2].z; w0.w -= zc[2].w;
                w1.x -= zc[3].x; w1.y -= zc[3].y; w1.z -= zc[3].z; w1.w -= zc[3].w;
            }
            stg256(&out[ob0 + (a * 3 + b) * F_DIM], v0, v1);
            stg256(&out[ob1 + (a * 3 + b) * F_DIM], w0, w1);
        }
    }
}

extern "C" void kernel_launch(void* const* d_in, const int* in_sizes, int n_in,
                              void* d_out, int out_size) {
    const float4* x = (const float4*)d_in[0];
    const float4* y = (const float4*)d_in[1];
    const float4* z = (const float4*)d_in[2];
    // d_in[3] is eye (identity) — value known, not needed.
    float4* out = (float4*)d_out;

    const int threads = 128;
    const int blocks = (NU + threads - 1) / threads;
    tp_block2_kernel<<<blocks, threads>>>(x, y, z, out);
}